// round 1
// baseline (speedup 1.0000x reference)
#include <cuda_runtime.h>
#include <cstdint>

#define N_NODES 100000
#define E_EDGES 1600000
#define IN_D 64
#define BOND_D 16
#define HID 128
#define OUT_D 64
#define COMBD 145
#define TILE_E 128
#define THREADS 512
#define COMB_PAD 149   // odd-ish stride -> conflict-free smem rows
#define H_PAD 129

// Runtime dtype flag for edge_index (1 = int32, 0 = int64)
__device__ int g_ei_is32;

__global__ void detect_index_dtype(const unsigned long long* __restrict__ ei) {
    // If data is int32, reading as u64 packs two indices; high word is nonzero
    // with overwhelming probability across 64 samples. If int64, all values < N.
    if (threadIdx.x == 0 && blockIdx.x == 0) {
        int is32 = 0;
        for (int i = 0; i < 64; ++i) {
            if (ei[i] > 0xFFFFFFFFull) { is32 = 1; break; }
        }
        g_ei_is32 = is32;
    }
}

__global__ void zero_out_kernel(float* __restrict__ p, int n) {
    int i = blockIdx.x * blockDim.x + threadIdx.x;
    if (i < n) p[i] = 0.f;
}

__device__ __forceinline__ float silu_f(float v) {
    return v / (1.f + __expf(-v));
}

__global__ __launch_bounds__(THREADS, 1)
void egnn_kernel(const float* __restrict__ x, const float* __restrict__ pos,
                 const float* __restrict__ edge_attr, const void* __restrict__ edge_index,
                 const float* __restrict__ W1x, const float* __restrict__ b1x,
                 const float* __restrict__ W2x, const float* __restrict__ b2x,
                 const float* __restrict__ W1p, const float* __restrict__ b1p,
                 const float* __restrict__ W2p, const float* __restrict__ b2p,
                 const float* __restrict__ W1e, const float* __restrict__ b1e,
                 const float* __restrict__ W2e, const float* __restrict__ b2e,
                 float* __restrict__ out)
{
    extern __shared__ float smem[];
    float* comb = smem;                          // TILE_E * COMB_PAD
    float* Hs   = comb + TILE_E * COMB_PAD;      // TILE_E * H_PAD
    float* Ws   = Hs + TILE_E * H_PAD;           // COMBD * HID (max reuse)
    float* b1s  = Ws + COMBD * HID;              // HID
    float* b2s  = b1s + HID;                     // OUT_D
    float* rps  = b2s + OUT_D;                   // TILE_E * 3
    int*   cols = (int*)(rps + TILE_E * 3);      // TILE_E
    int*   rows = cols + TILE_E;                 // TILE_E

    const int tid = threadIdx.x;
    const long long e_base = (long long)blockIdx.x * TILE_E;
    const int is32 = g_ei_is32;
    const int* ei32 = (const int*)edge_index;
    const long long* ei64 = (const long long*)edge_index;

    float* agg_x = out;
    float* agg_p = out + (size_t)N_NODES * OUT_D;
    float* e_out = agg_p + (size_t)N_NODES * 3;

    // ---- phase 0: indices, rel_pos, dist_sq ----
    for (int e = tid; e < TILE_E; e += THREADS) {
        long long ge = e_base + e;
        int r, c;
        if (is32) { r = ei32[ge]; c = ei32[E_EDGES + ge]; }
        else      { r = (int)ei64[ge]; c = (int)ei64[E_EDGES + ge]; }
        rows[e] = r; cols[e] = c;
        float dx = pos[r * 3 + 0] - pos[c * 3 + 0];
        float dy = pos[r * 3 + 1] - pos[c * 3 + 1];
        float dz = pos[r * 3 + 2] - pos[c * 3 + 2];
        rps[e * 3 + 0] = dx; rps[e * 3 + 1] = dy; rps[e * 3 + 2] = dz;
        comb[e * COMB_PAD + 144] = dx * dx + dy * dy + dz * dz;
    }
    __syncthreads();

    // ---- gather x[row], x[col] (float4 global loads) ----
    for (int idx = tid; idx < TILE_E * 16; idx += THREADS) {
        int e = idx >> 4, q = (idx & 15) * 4;
        float4 vr = *(const float4*)&x[(size_t)rows[e] * IN_D + q];
        float4 vc = *(const float4*)&x[(size_t)cols[e] * IN_D + q];
        float* cb = &comb[e * COMB_PAD];
        cb[q] = vr.x; cb[q + 1] = vr.y; cb[q + 2] = vr.z; cb[q + 3] = vr.w;
        cb[64 + q] = vc.x; cb[64 + q + 1] = vc.y; cb[64 + q + 2] = vc.z; cb[64 + q + 3] = vc.w;
    }
    // ---- edge_attr ----
    for (int idx = tid; idx < TILE_E * 4; idx += THREADS) {
        int e = idx >> 2, q = (idx & 3) * 4;
        float4 va = *(const float4*)&edge_attr[(size_t)(e_base + e) * BOND_D + q];
        float* cb = &comb[e * COMB_PAD + 128];
        cb[q] = va.x; cb[q + 1] = va.y; cb[q + 2] = va.z; cb[q + 3] = va.w;
    }

    const float* W1arr[3] = {W1x, W1p, W1e};
    const float* b1arr[3] = {b1x, b1p, b1e};

    for (int m = 0; m < 3; ++m) {
        __syncthreads();  // comb ready (m=0) / prior layer-2 done reading Ws,Hs

        // ---- load W1_m + b1_m into smem ----
        {
            const float4* src = (const float4*)W1arr[m];
            float4* dst = (float4*)Ws;
            for (int i = tid; i < COMBD * HID / 4; i += THREADS) dst[i] = src[i];
            if (tid < HID) b1s[tid] = b1arr[m][tid];
        }
        __syncthreads();

        // ---- layer 1: H = silu(comb @ W1 + b1), 4x8 register micro-tile ----
        {
            const int hgrp = tid & 15, egrp = tid >> 4;
            const int h0 = hgrp * 8, e0 = egrp * 4;
            float acc[4][8];
            #pragma unroll
            for (int i = 0; i < 4; i++)
                #pragma unroll
                for (int j = 0; j < 8; j++) acc[i][j] = 0.f;

            const float* c0 = &comb[(e0 + 0) * COMB_PAD];
            const float* c1 = &comb[(e0 + 1) * COMB_PAD];
            const float* c2 = &comb[(e0 + 2) * COMB_PAD];
            const float* c3 = &comb[(e0 + 3) * COMB_PAD];

            #pragma unroll 2
            for (int k = 0; k < COMBD; ++k) {
                float w[8];
                *(float4*)&w[0] = *(const float4*)&Ws[k * HID + h0];
                *(float4*)&w[4] = *(const float4*)&Ws[k * HID + h0 + 4];
                float cv[4] = {c0[k], c1[k], c2[k], c3[k]};
                #pragma unroll
                for (int i = 0; i < 4; i++)
                    #pragma unroll
                    for (int j = 0; j < 8; j++)
                        acc[i][j] = fmaf(cv[i], w[j], acc[i][j]);
            }
            #pragma unroll
            for (int i = 0; i < 4; i++)
                #pragma unroll
                for (int j = 0; j < 8; j++) {
                    float v = acc[i][j] + b1s[h0 + j];
                    Hs[(e0 + i) * H_PAD + h0 + j] = silu_f(v);
                }
        }
        __syncthreads();

        // ---- layer 2 (+ apply) ----
        if (m == 0) {
            for (int i = tid; i < HID * OUT_D / 4; i += THREADS)
                ((float4*)Ws)[i] = ((const float4*)W2x)[i];
            if (tid < OUT_D) b2s[tid] = b2x[tid];
            __syncthreads();

            const int ogrp = tid & 15, egrp = tid >> 4;
            const int o0 = ogrp * 4, e0 = egrp * 4;
            float acc[4][4];
            #pragma unroll
            for (int i = 0; i < 4; i++)
                #pragma unroll
                for (int j = 0; j < 4; j++) acc[i][j] = 0.f;

            const float* h0p = &Hs[(e0 + 0) * H_PAD];
            const float* h1p = &Hs[(e0 + 1) * H_PAD];
            const float* h2p = &Hs[(e0 + 2) * H_PAD];
            const float* h3p = &Hs[(e0 + 3) * H_PAD];

            #pragma unroll 2
            for (int k = 0; k < HID; ++k) {
                float4 w = *(const float4*)&Ws[k * OUT_D + o0];
                float hv[4] = {h0p[k], h1p[k], h2p[k], h3p[k]};
                #pragma unroll
                for (int i = 0; i < 4; i++) {
                    acc[i][0] = fmaf(hv[i], w.x, acc[i][0]);
                    acc[i][1] = fmaf(hv[i], w.y, acc[i][1]);
                    acc[i][2] = fmaf(hv[i], w.z, acc[i][2]);
                    acc[i][3] = fmaf(hv[i], w.w, acc[i][3]);
                }
            }
            #pragma unroll
            for (int i = 0; i < 4; i++) {
                size_t base = (size_t)cols[e0 + i] * OUT_D + o0;
                #pragma unroll
                for (int j = 0; j < 4; j++)
                    atomicAdd(&agg_x[base + j], acc[i][j] + b2s[o0 + j]);
            }
        } else if (m == 1) {
            if (tid < HID) Ws[tid] = W2p[tid];
            if (tid == 0) b2s[0] = W2p == nullptr ? 0.f : b2p[0];
            __syncthreads();
            if (tid < TILE_E) {
                float s = b2s[0];
                const float* hrow = &Hs[tid * H_PAD];
                #pragma unroll 4
                for (int k = 0; k < HID; ++k) s = fmaf(hrow[k], Ws[k], s);
                int c = cols[tid];
                atomicAdd(&agg_p[(size_t)c * 3 + 0], s * rps[tid * 3 + 0]);
                atomicAdd(&agg_p[(size_t)c * 3 + 1], s * rps[tid * 3 + 1]);
                atomicAdd(&agg_p[(size_t)c * 3 + 2], s * rps[tid * 3 + 2]);
            }
        } else {
            for (int i = tid; i < HID * BOND_D / 4; i += THREADS)
                ((float4*)Ws)[i] = ((const float4*)W2e)[i];
            if (tid < BOND_D) b2s[tid] = b2e[tid];
            __syncthreads();

            const int og = (tid & 3) * 4, e = tid >> 2;
            float a0 = 0.f, a1 = 0.f, a2 = 0.f, a3 = 0.f;
            const float* hrow = &Hs[e * H_PAD];
            #pragma unroll 4
            for (int k = 0; k < HID; ++k) {
                float hv = hrow[k];
                float4 w = *(const float4*)&Ws[k * BOND_D + og];
                a0 = fmaf(hv, w.x, a0);
                a1 = fmaf(hv, w.y, a1);
                a2 = fmaf(hv, w.z, a2);
                a3 = fmaf(hv, w.w, a3);
            }
            float4 o;
            o.x = a0 + b2s[og];     o.y = a1 + b2s[og + 1];
            o.z = a2 + b2s[og + 2]; o.w = a3 + b2s[og + 3];
            *(float4*)&e_out[((size_t)e_base + e) * BOND_D + og] = o;
        }
    }
}

extern "C" void kernel_launch(void* const* d_in, const int* in_sizes, int n_in,
                              void* d_out, int out_size) {
    const float* x         = (const float*)d_in[0];
    const float* pos       = (const float*)d_in[1];
    const float* edge_attr = (const float*)d_in[2];
    const void*  edge_idx  = d_in[3];
    const float* W1x = (const float*)d_in[4];
    const float* b1x = (const float*)d_in[5];
    const float* W2x = (const float*)d_in[6];
    const float* b2x = (const float*)d_in[7];
    const float* W1p = (const float*)d_in[8];
    const float* b1p = (const float*)d_in[9];
    const float* W2p = (const float*)d_in[10];
    const float* b2p = (const float*)d_in[11];
    const float* W1e = (const float*)d_in[12];
    const float* b1e = (const float*)d_in[13];
    const float* W2e = (const float*)d_in[14];
    const float* b2e = (const float*)d_in[15];
    float* out = (float*)d_out;

    // smem: comb + H + W + b1 + b2 + relpos (floats) + cols/rows (ints)
    size_t smem_floats = (size_t)TILE_E * COMB_PAD + (size_t)TILE_E * H_PAD +
                         (size_t)COMBD * HID + HID + OUT_D + (size_t)TILE_E * 3;
    size_t smem_bytes = smem_floats * sizeof(float) + 2 * TILE_E * sizeof(int);

    cudaFuncSetAttribute(egnn_kernel,
                         cudaFuncAttributeMaxDynamicSharedMemorySize,
                         (int)smem_bytes);

    detect_index_dtype<<<1, 32>>>((const unsigned long long*)edge_idx);

    int nz = N_NODES * OUT_D + N_NODES * 3;
    zero_out_kernel<<<(nz + 255) / 256, 256>>>(out, nz);

    int nblocks = E_EDGES / TILE_E;   // 12500
    egnn_kernel<<<nblocks, THREADS, smem_bytes>>>(
        x, pos, edge_attr, edge_idx,
        W1x, b1x, W2x, b2x,
        W1p, b1p, W2p, b2p,
        W1e, b1e, W2e, b2e,
        out);
}